// round 10
// baseline (speedup 1.0000x reference)
#include <cuda_runtime.h>
#include <cuda_fp16.h>
#include <cstdint>
#include <climits>

// VQ-VAE quantizer: fp16x2 HFMA2 scan (2 MAC per fma-pipe slot) + sound margin
// + bit-exact fp32 refinement (identical arithmetic to the rel_err=0.0 round-4 path).
//
//  scan: v(t,k) = dot(x_t/xmax_t, c_k*1024) via 32 HFMA2 (two interleaved fp16
//  chains, fp32 combine). dist = sx + sc2 - 2*(xmax/1024)*v_true, so argmin dist
//  = argmax v up to (sc2 span + fp16 error). Sound margin M_v selects candidates;
//  per-(token,column) top-2 bounds who can hide; selected codes re-scored exactly.
//
//  R9 crash root cause fixed: shared-space u32 addresses (cvta.to.shared) were
//  dereferenced as generic pointers. Now u32 addresses feed cp.async ONLY; all
//  smem loads go through generic pointers derived from the __shared__ array.

typedef unsigned long long u64;
typedef unsigned int u32;

#define D        64
#define NCODES   1024
#define BT       128
#define NCH      16            // chunks of 64 codes
#define CODES_CH 64
#define NBLOCKS  2048

// ---- smem byte offsets ----
#define SM_XT    0             // half2 [32 g][128 tokens]      16384
#define SM_B0    16384         // half2 [32 g][64 codes]         8192
#define SM_B1    24576         //                                8192
#define SM_SC2   32768         // f32[1024]                      4096
#define SM_M1    36864         // f32[128][8]                    4096
#define SM_M2    40960         // f32[128][8]                    4096
#define SM_I1    45056         // i32[128][8]                    4096
#define SM_MV    49152         // f32[128]                        512
#define SM_SX    49664         // f32[128]                        512
#define SM_BIDX  50176         // i32[128]                        512
#define SM_PART  50688         // u64[128]                       1024
#define SMEM_TOTAL 51712

__device__ u32   g_ch2[NCH * 32 * CODES_CH];  // fp16x2 codebook, [chunk][g][code]
__device__ float g_sumc2[NCODES];
__device__ float g_sabsb[NCODES];
__device__ float g_SBC;                        // max_k sum |b_h(k)|
__device__ float g_sc2span;
__device__ u64   g_block_loss[NBLOCKS];

__device__ __forceinline__ u32 smem_u32(const void* p) {
    u32 a; asm("{ .reg .u64 t; cvta.to.shared.u64 t, %1; cvt.u32.u64 %0, t; }" : "=r"(a) : "l"(p));
    return a;
}
__device__ __forceinline__ void cp16(u32 saddr, const void* g) {
    asm volatile("{ .reg .u64 gp; cvta.to.global.u64 gp, %1;"
                 " cp.async.cg.shared.global [%0], [gp], 16; }"
                 :: "r"(saddr), "l"(g) : "memory");
}
#define CP_COMMIT() asm volatile("cp.async.commit_group;" ::: "memory")
#define CP_WAIT1()  asm volatile("cp.async.wait_group 1;" ::: "memory")
#define CP_WAIT0()  asm volatile("cp.async.wait_group 0;" ::: "memory")

__device__ __forceinline__ __half2 as_h2(u32 v) { return *reinterpret_cast<__half2*>(&v); }

// Exact re-score: arithmetic identical to the round-4 (rel_err = 0.0) kernel.
__device__ __forceinline__ u64 exact_key(const float* __restrict__ xr,
                                         const float* __restrict__ cb,
                                         const float* __restrict__ sc2s,
                                         float sx, int ci) {
    const float* cr = cb + (size_t)ci * D;
    float dot = 0.f;
#pragma unroll 16
    for (int d = 0; d < D; d++) dot = fmaf(xr[d], cr[d], dot);
    float dist = fmaf(-2.f, dot, sx + sc2s[ci]);
    return ((u64)__float_as_uint(dist) << 32) | (u32)ci;
}

// ---------------------------------------------------------------------------
// Prep 1 (8 x 128): fp16 codebook (b = c*1024, pow-2 exact scale), sumc2
// (reference-order fma), sum|b_h|.
// ---------------------------------------------------------------------------
__global__ void prep_kernel(const float* __restrict__ cb) {
    const int k  = blockIdx.x * 128 + threadIdx.x;
    const int ch = k >> 6, j = k & 63;
    float s = 0.f, sab = 0.f;
#pragma unroll
    for (int g = 0; g < 32; g++) {
        float v0 = cb[(size_t)k * D + 2 * g];
        float v1 = cb[(size_t)k * D + 2 * g + 1];
        s = fmaf(v0, v0, s);
        s = fmaf(v1, v1, s);
        __half h0 = __float2half_rn(v0 * 1024.f);
        __half h1 = __float2half_rn(v1 * 1024.f);
        sab += fabsf(__half2float(h0)) + fabsf(__half2float(h1));
        __half2 p = __halves2half2(h0, h1);
        g_ch2[(ch * 32 + g) * CODES_CH + j] = *reinterpret_cast<u32*>(&p);
    }
    g_sumc2[k] = s;
    g_sabsb[k] = sab;
}

// ---------------------------------------------------------------------------
// Prep 2 (1 x 256): SBC = max sum|b|, sc2 span.
// ---------------------------------------------------------------------------
__global__ void prep2_kernel() {
    __shared__ float ra[256], rb[256], rc[256];
    const int t = threadIdx.x;
    float ma = -1e30f, mb = -1e30f, mc = 1e30f;
    for (int i = t; i < NCODES; i += 256) {
        ma = fmaxf(ma, g_sabsb[i]);
        float s = g_sumc2[i];
        mb = fmaxf(mb, s);
        mc = fminf(mc, s);
    }
    ra[t] = ma; rb[t] = mb; rc[t] = mc;
    __syncthreads();
    for (int st = 128; st > 0; st >>= 1) {
        if (t < st) {
            ra[t] = fmaxf(ra[t], ra[t + st]);
            rb[t] = fmaxf(rb[t], rb[t + st]);
            rc[t] = fminf(rc[t], rc[t + st]);
        }
        __syncthreads();
    }
    if (t == 0) { g_SBC = ra[0]; g_sc2span = rb[0] - rc[0]; }
}

// ---------------------------------------------------------------------------
// Main kernel: 256 threads, 128 tokens/block. ty=tid>>3 owns 4 tokens,
// tx=tid&7 owns 8 codes per 64-code chunk (=> 8 columns of 128 codes/token).
// ---------------------------------------------------------------------------
__global__ __launch_bounds__(256, 2)
void vq_kernel(const float* __restrict__ x,
               const float* __restrict__ cb,
               float* __restrict__ out_q,
               float* __restrict__ out_idx) {
    extern __shared__ char smem[];
    const u32 sb  = smem_u32(smem);          // shared-space addr: cp.async ONLY
    const int tid = threadIdx.x;
    const int t0  = blockIdx.x * BT;

    float* sc2s = (float*)(smem + SM_SC2);
    float* M1s  = (float*)(smem + SM_M1);
    float* M2s  = (float*)(smem + SM_M2);
    int*   I1s  = (int*)(smem + SM_I1);
    float* MVs  = (float*)(smem + SM_MV);
    float* SXs  = (float*)(smem + SM_SX);
    int*   bidx = (int*)(smem + SM_BIDX);
    u64*   part = (u64*)(smem + SM_PART);

    // Prefetch code chunk 0 (8 KB)
    for (u32 off = tid * 16; off < 32 * CODES_CH * 4; off += 256 * 16)
        cp16(sb + SM_B0 + off, (const char*)g_ch2 + off);
    CP_COMMIT();

    for (int i = tid; i < NCODES; i += 256) sc2s[i] = g_sumc2[i];

    // Per-token prologue (tid < 128): exact sx (ref order), stats, fp16 tile, margin
    if (tid < BT) {
        const float* xr = x + (size_t)(t0 + tid) * D;
        float xmax = 1e-30f, s1 = 0.f, sx = 0.f;
#pragma unroll 16
        for (int d = 0; d < D; d++) {
            float v = xr[d];
            sx = fmaf(v, v, sx);
            float a = fabsf(v);
            xmax = fmaxf(xmax, a);
            s1 += a;
        }
        SXs[tid] = sx;
        const float inv = 1.f / xmax;
#pragma unroll
        for (int g = 0; g < 32; g++) {
            __half2 p = __halves2half2(__float2half_rn(xr[2 * g] * inv),
                                       __float2half_rn(xr[2 * g + 1] * inv));
            *(u32*)(smem + SM_XT + g * 512 + tid * 4) = *reinterpret_cast<u32*>(&p);
        }
        // Sound margin in v units. Two 16-step fp16 chains per pair; running sums
        // bounded by P; per-op err <= ulp16(P+0.75)/2; input cvt err 2^-11*(S1x+SBC).
        const float S1x = s1 * inv;
        const float SBC = g_SBC;
        float P  = fminf(S1x * 1.01f + 0.1f, SBC * 1.01f + 0.1f);
        float u  = exp2f(floorf(log2f(P + 0.75f)) - 10.f);
        float E  = 32.f * u + 4.8828e-4f * (S1x + SBC) + 2e-3f;
        MVs[tid] = 2.f * E + (g_sc2span + 4e-5f) * (1024.f / (2.f * xmax)) + 0.02f;
    }

    const int ty = tid >> 3, tx = tid & 7;
    const char* a_base = smem + SM_XT + ty * 16;      // + g*512 (generic ptr, LDS.128)
    const int   b_off  = tx * 32;                     // + g*256 within buffer

    float m1[4], m2[4];
    int   i1[4];
#pragma unroll
    for (int i = 0; i < 4; i++) { m1[i] = -3.4e38f; m2[i] = -3.4e38f; i1[i] = 0; }

    for (int ch = 0; ch < NCH; ch++) {
        if (ch + 1 < NCH) {   // prefetch next chunk into other buffer
            const u32 dst = sb + (((ch + 1) & 1) ? SM_B1 : SM_B0);
            const char* src = (const char*)g_ch2 + (size_t)(ch + 1) * 8192;
            for (u32 off = tid * 16; off < 8192; off += 256 * 16)
                cp16(dst + off, src + off);
            CP_COMMIT();
            CP_WAIT1();       // current chunk's group complete
        } else {
            CP_WAIT0();
        }
        __syncthreads();      // publish copies (and, ch=0: x tile) to all threads

        const char* b_base = smem + (((ch & 1) ? SM_B1 : SM_B0) + b_off);

        __half2 acc[2][4][8];
#pragma unroll
        for (int i = 0; i < 4; i++)
#pragma unroll
            for (int j = 0; j < 8; j++) {
                acc[0][i][j] = __float2half2_rn(0.f);
                acc[1][i][j] = __float2half2_rn(0.f);
            }

#pragma unroll 4
        for (int g = 0; g < 32; g++) {
            const uint4 av  = *(const uint4*)(a_base + g * 512);
            const uint4 bv0 = *(const uint4*)(b_base + g * 256);
            const uint4 bv1 = *(const uint4*)(b_base + g * 256 + 16);
            __half2 ah[4] = {as_h2(av.x), as_h2(av.y), as_h2(av.z), as_h2(av.w)};
            __half2 bh[8] = {as_h2(bv0.x), as_h2(bv0.y), as_h2(bv0.z), as_h2(bv0.w),
                             as_h2(bv1.x), as_h2(bv1.y), as_h2(bv1.z), as_h2(bv1.w)};
            const int s = g & 1;
#pragma unroll
            for (int i = 0; i < 4; i++)
#pragma unroll
                for (int j = 0; j < 8; j++)
                    acc[s][i][j] = __hfma2(ah[i], bh[j], acc[s][i][j]);
        }

        // Finalize chunk: fp32 combine (fixed order) + per-(token,column) top-2
        const int cbase = ch * CODES_CH + tx * 8;
#pragma unroll
        for (int i = 0; i < 4; i++)
#pragma unroll
            for (int j = 0; j < 8; j++) {
                float v = ((__low2float(acc[0][i][j]) + __high2float(acc[0][i][j]))
                           + __low2float(acc[1][i][j])) + __high2float(acc[1][i][j]);
                if (v > m2[i]) {
                    if (v > m1[i]) { m2[i] = m1[i]; m1[i] = v; i1[i] = cbase + j; }
                    else           { m2[i] = v; }
                }
            }
        __syncthreads();   // buffer fully consumed before next iter's prefetch reuses it
    }

#pragma unroll
    for (int i = 0; i < 4; i++) {
        const int t = ty * 4 + i;
        M1s[t * 8 + tx] = m1[i];
        M2s[t * 8 + tx] = m2[i];
        I1s[t * 8 + tx] = i1[i];
    }
    __syncthreads();

    // ---- Refinement (token = tid < 128) ----
    if (tid < BT) {
        const int t = tid;
        float gm = -3.4e38f;
#pragma unroll
        for (int c = 0; c < 8; c++) gm = fmaxf(gm, M1s[t * 8 + c]);
        const float thr = gm - MVs[t];

        const float* xr = x + (size_t)(t0 + t) * D;
        const float  sx = SXs[t];
        u64 best = 0xFFFFFFFFFFFFFFFFull;
        for (int c = 0; c < 8; c++) {
            if (M1s[t * 8 + c] < thr) continue;
            if (M2s[t * 8 + c] >= thr) {
                // >=2 in-margin codes in this 128-code column: exact-rescore it all
                // (any deeper in-margin code forces m2 >= thr, so this is sound).
                for (int ch2 = 0; ch2 < NCH; ch2++) {
                    const int kb = ch2 * CODES_CH + c * 8;
#pragma unroll
                    for (int j = 0; j < 8; j++) {
                        u64 key = exact_key(xr, cb, sc2s, sx, kb + j);
                        if (key < best) best = key;
                    }
                }
            } else {
                u64 key = exact_key(xr, cb, sc2s, sx, I1s[t * 8 + c]);
                if (key < best) best = key;
            }
        }

        const int   besti = (int)(best & 0xFFFFFFFFull);
        const float bestd = __uint_as_float((u32)(best >> 32));
        bidx[t] = besti;
        out_idx[t0 + t] = (float)besti;
        part[t] = (u64)llrintf(bestd * 1073741824.f);   // Q30 fixed point
    }
    __syncthreads();

    if (tid == 0) {
        u64 s = 0;
        for (int k = 0; k < BT; k++) s += part[k];
        g_block_loss[blockIdx.x] = s;                   // fresh write: deterministic
    }

    // Quantized output, coalesced; straight-through rounding x + (q - x)
    for (int idx = tid; idx < BT * D; idx += 256) {
        int t = idx >> 6, d = idx & 63;
        float q  = __ldg(&cb[(size_t)bidx[t] * D + d]);
        float xv = x[(size_t)(t0 + t) * D + d];
        out_q[(size_t)(t0 + t) * D + d] = xv + (q - xv);
    }
}

// ---------------------------------------------------------------------------
// Finalize: loss = m + 0.25*m, m = mean(best_dist) over N*D elements
// ---------------------------------------------------------------------------
__global__ void finalize_kernel(float* __restrict__ out_loss, double inv_count) {
    __shared__ u64 sh[256];
    u64 s = 0;
    for (int i = threadIdx.x; i < NBLOCKS; i += 256) s += g_block_loss[i];
    sh[threadIdx.x] = s;
    __syncthreads();
    for (int st = 128; st > 0; st >>= 1) {
        if (threadIdx.x < st) sh[threadIdx.x] += sh[threadIdx.x + st];
        __syncthreads();
    }
    if (threadIdx.x == 0) {
        double tot = (double)sh[0] * (1.0 / 1073741824.0);
        float  m   = (float)(tot * inv_count);
        out_loss[0] = m + 0.25f * m;
    }
}

extern "C" void kernel_launch(void* const* d_in, const int* in_sizes, int n_in,
                              void* d_out, int out_size) {
    const float* x  = (const float*)d_in[0];
    const float* cb = (const float*)d_in[1];
    float* out = (float*)d_out;

    const int n = in_sizes[0] / D;            // 262144 tokens
    float* out_q    = out;
    float* out_loss = out + (size_t)n * D;
    float* out_idx  = out_loss + 1;

    cudaFuncSetAttribute(vq_kernel, cudaFuncAttributeMaxDynamicSharedMemorySize,
                         SMEM_TOTAL);

    prep_kernel<<<8, 128>>>(cb);
    prep2_kernel<<<1, 256>>>();
    vq_kernel<<<n / BT, 256, SMEM_TOTAL>>>(x, cb, out_q, out_idx);
    finalize_kernel<<<1, 256>>>(out_loss, 1.0 / ((double)n * D));
}